// round 12
// baseline (speedup 1.0000x reference)
#include <cuda_runtime.h>
#include <cuda_bf16.h>

#define FULL 0xffffffffu

namespace {
constexpr int NB   = 32;
constexpr int NP   = 32;
constexpr int DD   = 12;
constexpr int PP   = 32;
constexpr int LL   = 1024;
constexpr int LOUT = 32;
constexpr int CPL  = 8;            // cols per lane
constexpr int CP2  = CPL / 2;      // packed f32x2 pairs per lane
constexpr int WBLK = 32 * CPL;     // 256 cols per warp
constexpr int NBLK = LL / WBLK;    // 4 warps per (b,n)
constexpr int DREG = 9;            // x dims kept in registers
constexpr int DSM  = DD - DREG;    // x dims kept in shared memory (3)
constexpr float BIGV = 1e30f;
}

typedef unsigned long long u64;

// Blackwell packed fp32x2 ops (FFMA2/FADD2 in SASS — only reachable via PTX).
__device__ __forceinline__ u64 pack2(float lo, float hi) {
    u64 r; asm("mov.b64 %0, {%1, %2};" : "=l"(r) : "f"(lo), "f"(hi)); return r;
}
__device__ __forceinline__ void unpack2(u64 v, float& lo, float& hi) {
    asm("mov.b64 {%0, %1}, %2;" : "=f"(lo), "=f"(hi) : "l"(v));
}
__device__ __forceinline__ u64 ffma2(u64 a, u64 b, u64 c) {
    u64 d; asm("fma.rn.f32x2 %0, %1, %2, %3;" : "=l"(d) : "l"(a), "l"(b), "l"(c)); return d;
}
__device__ __forceinline__ u64 fadd2(u64 a, u64 b) {
    u64 d; asm("add.rn.f32x2 %0, %1, %2;" : "=l"(d) : "l"(a), "l"(b)); return d;
}

// One CTA (4 warps) per (b, n); warp w owns column block w (256 cols).
// Diagonal wavefront (step t: warp w does row i = t - w), one __syncthreads
// per step; carries cross warps via barrier-ordered smem (proven faster than
// the lock-free handoff in R10/R11).
//
// Register diet to reach 4 CTAs/SM (128-reg cap): pattern table lives in smem
// as packed (-2p,-2p) u64 (replaces 13 broadcast shfls + packs per step with
// 13 broadcast LDS.64), and 3 of the 12 x-dims live in smem with a
// conflict-free [k2][lane] u64 layout (12 per-lane LDS.64 per step).
//
// Row recurrence (w == 1 exactly, RHO = 1.0):
//   cur[j] = c[j] + min(m[j], cur[j-1]),  m[j] = min(D[i-1,j-1], D[i-1,j])
// as composition of affine-min maps f_j(v) = min(beta_j, v + alpha_j),
// (f2 o f1) = (alpha1+alpha2, min(beta2, beta1+alpha2)): one composite
// Kogge-Stone scan (5 hops). Cost rows use packed f32x2 FMAs.
__global__ void __launch_bounds__(128, 4)
dtw_fused_kernel(const float* __restrict__ x,
                 const float* __restrict__ patts,
                 float* __restrict__ out)
{
    const int gid  = blockIdx.x;        // 0..1023
    const int b    = gid >> 5;
    const int n    = gid & 31;
    const int w    = threadIdx.x >> 5;  // column block 0..3
    const int lane = threadIdx.x & 31;

    __shared__ u64 pt[PP][DD];                 // packed (-2*patt, -2*patt)
    __shared__ u64 ptp2[PP];                   // packed (p2, p2)
    __shared__ u64 xs[NBLK][DSM][CP2][32];     // spilled x dims, [k2][lane] u64
    __shared__ float carry[NBLK - 1][PP];      // carry[w][i] = D[i][(w+1)*WBLK-1]

    // ---- pattern table (warp 0 builds; others proceed to x load) ----
    if (threadIdx.x < PP) {
        const int i = threadIdx.x;
        const float* pp = patts + n * (DD * PP) + i;
        float s2 = 0.0f;
        #pragma unroll
        for (int d = 0; d < DD; ++d) {
            float v = pp[d * PP];
            s2 = fmaf(v, v, s2);
            float m2 = -2.0f * v;
            pt[i][d] = pack2(m2, m2);
        }
        ptp2[i] = pack2(s2, s2);
    }

    // ---- x chunk for this warp's column block ----
    const float* xb = x + b * (DD * LL);
    const int j0 = w * WBLK;
    u64 xp[DREG][CP2];
    u64 px2[CP2];
    {
        u64 z = pack2(0.0f, 0.0f);
        #pragma unroll
        for (int k2 = 0; k2 < CP2; ++k2) px2[k2] = z;
    }
    #pragma unroll
    for (int d = 0; d < DD; ++d) {
        const float* px = xb + d * LL + j0 + CPL * lane;
        float4 v0 = *reinterpret_cast<const float4*>(px);
        float4 v1 = *reinterpret_cast<const float4*>(px + 4);
        u64 a0 = pack2(v0.x, v0.y);
        u64 a1 = pack2(v0.z, v0.w);
        u64 a2 = pack2(v1.x, v1.y);
        u64 a3 = pack2(v1.z, v1.w);
        px2[0] = ffma2(a0, a0, px2[0]);
        px2[1] = ffma2(a1, a1, px2[1]);
        px2[2] = ffma2(a2, a2, px2[2]);
        px2[3] = ffma2(a3, a3, px2[3]);
        if (d < DREG) {
            xp[d][0] = a0; xp[d][1] = a1; xp[d][2] = a2; xp[d][3] = a3;
        } else {
            xs[w][d - DREG][0][lane] = a0;
            xs[w][d - DREG][1][lane] = a1;
            xs[w][d - DREG][2][lane] = a2;
            xs[w][d - DREG][3][lane] = a3;
        }
    }
    __syncthreads();   // pattern table + smem x ready

    float* outb = out + ((b * NP + n) * PP) * LOUT;
    float Dp[CPL];   // previous DP row for this warp's block

    #pragma unroll 1
    for (int t = 0; t < PP + NBLK - 1; ++t) {
        const int i = t - w;
        if (i >= 0 && i < PP) {
            // ---- cost row c[k] (alpha), packed f32x2 ----
            u64 cc[CP2];
            {
                u64 p22 = ptp2[i];
                #pragma unroll
                for (int k2 = 0; k2 < CP2; ++k2) cc[k2] = fadd2(p22, px2[k2]);
            }
            #pragma unroll
            for (int d = 0; d < DREG; ++d) {
                u64 pbb = pt[i][d];
                #pragma unroll
                for (int k2 = 0; k2 < CP2; ++k2)
                    cc[k2] = ffma2(pbb, xp[d][k2], cc[k2]);
            }
            #pragma unroll
            for (int dd = 0; dd < DSM; ++dd) {
                u64 pbb = pt[i][DREG + dd];
                #pragma unroll
                for (int k2 = 0; k2 < CP2; ++k2)
                    cc[k2] = ffma2(pbb, xs[w][dd][k2][lane], cc[k2]);
            }
            float c[CPL];
            #pragma unroll
            for (int k2 = 0; k2 < CP2; ++k2)
                unpack2(cc[k2], c[2 * k2], c[2 * k2 + 1]);

            // ---- boundary carries (barrier-ordered smem) ----
            float bl, bm;  // D[i][j0-1], D[i-1][j0-1]
            if (w == 0) {
                bl = (i == 0) ? 0.0f : BIGV;   // D[0,0] seed enters as v
                bm = BIGV;                      // D[i-1][-1] is always OOR
            } else {
                bl = carry[w - 1][i];
                bm = (i > 0) ? carry[w - 1][i - 1] : BIGV;
            }

            // ---- local inclusive composites (A = prefix sum of c, B = bound) ----
            float A[CPL], Bv[CPL];
            float shin = __shfl_up_sync(FULL, Dp[CPL - 1], 1);
            if (i == 0) {
                A[0] = c[0]; Bv[0] = BIGV;
                #pragma unroll
                for (int k = 1; k < CPL; ++k) { A[k] = A[k - 1] + c[k]; Bv[k] = BIGV; }
            } else {
                float m0 = fminf((lane == 0) ? bm : shin, Dp[0]);
                A[0]  = c[0];
                Bv[0] = c[0] + m0;
                #pragma unroll
                for (int k = 1; k < CPL; ++k) {
                    float mk = fminf(Dp[k - 1], Dp[k]);
                    A[k]  = A[k - 1] + c[k];
                    Bv[k] = fminf(c[k] + mk, Bv[k - 1] + c[k]);
                }
            }

            // ---- single composite warp scan over lane maps ----
            float Aw = A[CPL - 1], Bw = Bv[CPL - 1];
            #pragma unroll
            for (int o = 1; o < 32; o <<= 1) {
                float Au = __shfl_up_sync(FULL, Aw, o);
                float Bu = __shfl_up_sync(FULL, Bw, o);
                if (lane >= o) {
                    Bw = fminf(Bw, Bu + Aw);  // uses pre-update Aw
                    Aw = Aw + Au;
                }
            }
            float Ae = __shfl_up_sync(FULL, Aw, 1);
            float Be = __shfl_up_sync(FULL, Bw, 1);
            float vin = (lane == 0) ? bl : fminf(Be, bl + Ae);

            // ---- outputs: cur[k] = min(B[k], vin + A[k]) ----
            float cur[CPL];
            #pragma unroll
            for (int k = 0; k < CPL; ++k)
                cur[k] = fminf(Bv[k], vin + A[k]);

            // ---- publish carry for the warp to the right ----
            if (w < NBLK - 1 && lane == 31) carry[w][i] = cur[CPL - 1];

            // ---- output: cols 992..1023 = lanes 28..31 of last warp ----
            if (w == NBLK - 1 && lane >= 28) {
                float* po = outb + i * LOUT + (lane - 28) * CPL;
                *reinterpret_cast<float4*>(po)     = make_float4(cur[0], cur[1], cur[2], cur[3]);
                *reinterpret_cast<float4*>(po + 4) = make_float4(cur[4], cur[5], cur[6], cur[7]);
            }

            #pragma unroll
            for (int k = 0; k < CPL; ++k) Dp[k] = cur[k];
        }
        __syncthreads();
    }
}

extern "C" void kernel_launch(void* const* d_in, const int* in_sizes, int n_in,
                              void* d_out, int out_size) {
    const float* x     = (const float*)d_in[0];   // [32, 12, 1024]
    const float* patts = (const float*)d_in[1];   // [32, 12, 32]
    float* out = (float*)d_out;                   // [32, 32, 32, 32]
    (void)in_sizes; (void)n_in; (void)out_size;
    dtw_fused_kernel<<<NB * NP, 128>>>(x, patts, out);
}

// round 14
// speedup vs baseline: 1.5381x; 1.5381x over previous
#include <cuda_runtime.h>
#include <cuda_bf16.h>

#define FULL 0xffffffffu

namespace {
constexpr int NB   = 32;
constexpr int NP   = 32;
constexpr int DD   = 12;
constexpr int PP   = 32;
constexpr int LL   = 1024;
constexpr int LOUT = 32;
constexpr int CPL  = 8;            // cols per lane
constexpr int CP2  = CPL / 2;      // packed f32x2 pairs per lane
constexpr int WBLK = 32 * CPL;     // 256 cols per warp
constexpr int NBLK = LL / WBLK;    // 4 warps per (b,n)
constexpr float BIGV = 1e30f;
}

typedef unsigned long long u64;

// Blackwell packed fp32x2 ops (FFMA2/FADD2 in SASS — only reachable via PTX).
__device__ __forceinline__ u64 pack2(float lo, float hi) {
    u64 r; asm("mov.b64 %0, {%1, %2};" : "=l"(r) : "f"(lo), "f"(hi)); return r;
}
__device__ __forceinline__ void unpack2(u64 v, float& lo, float& hi) {
    asm("mov.b64 {%0, %1}, %2;" : "=f"(lo), "=f"(hi) : "l"(v));
}
__device__ __forceinline__ u64 ffma2(u64 a, u64 b, u64 c) {
    u64 d; asm("fma.rn.f32x2 %0, %1, %2, %3;" : "=l"(d) : "l"(a), "l"(b), "l"(c)); return d;
}
__device__ __forceinline__ u64 fadd2(u64 a, u64 b) {
    u64 d; asm("add.rn.f32x2 %0, %1, %2;" : "=l"(d) : "l"(a), "l"(b)); return d;
}
// Both-blocking named barrier over 64 threads (2 warps). SAFE pattern:
// every participant blocks, all hits are matched — no bar.arrive run-ahead.
__device__ __forceinline__ void bar_pair(int id) {
    asm volatile("bar.sync %0, 64;" :: "r"(id) : "memory");
}

// One CTA (4 warps) per (b, n); warp w owns column block w (256 cols).
// Pairwise producer/consumer pipeline: warps (w-1, w) share named barrier id=w
// (64 threads, both blocking). Each warp's iteration: top bar(w) => rows
// published by warp w-1 for this step are visible; compute TWO rows; publish;
// bottom bar(w+1). Linear chain, consistent order => deadlock-free; adjacent
// skew is exactly one 2-row step; warp 0 never waits on warps 2..3 directly.
//
// Row recurrence (w == 1 exactly, RHO = 1.0):
//   cur[j] = c[j] + min(m[j], cur[j-1]),  m[j] = min(D[i-1,j-1], D[i-1,j])
// as composition of affine-min maps f_j(v) = min(beta_j, v + alpha_j),
// (f2 o f1) = (alpha1+alpha2, min(beta2, beta1+alpha2)): one composite
// Kogge-Stone scan (5 hops). Cost rows: packed f32x2 FMAs; pattern operands
// come from a smem table ((-2p,-2p) u64 + packed p2) via broadcast LDS.64 —
// x stays entirely in registers (R12 showed spilling x to smem is fatal).
__global__ void __launch_bounds__(128, 3)
dtw_fused_kernel(const float* __restrict__ x,
                 const float* __restrict__ patts,
                 float* __restrict__ out)
{
    const int gid  = blockIdx.x;        // 0..1023
    const int b    = gid >> 5;
    const int n    = gid & 31;
    const int w    = threadIdx.x >> 5;  // column block 0..3
    const int lane = threadIdx.x & 31;

    __shared__ u64   pt[PP][DD];            // packed (-2*patt, -2*patt)
    __shared__ u64   ptp2[PP];              // packed (p2, p2)
    __shared__ float carry[NBLK - 1][PP];   // carry[w][i] = D[i][(w+1)*WBLK-1]

    // ---- pattern table: warp 0, one thread per pattern row ----
    if (threadIdx.x < PP) {
        const int i = threadIdx.x;
        const float* pp = patts + n * (DD * PP) + i;
        float s2 = 0.0f;
        #pragma unroll
        for (int d = 0; d < DD; ++d) {
            float v = pp[d * PP];
            s2 = fmaf(v, v, s2);
            float m2 = -2.0f * v;
            pt[i][d] = pack2(m2, m2);
        }
        ptp2[i] = pack2(s2, s2);
    }

    // ---- x chunk for this warp's column block (registers, packed f32x2) ----
    const float* xb = x + b * (DD * LL);
    const int j0 = w * WBLK;
    u64 xp[DD][CP2];
    u64 px2[CP2];
    {
        u64 z = pack2(0.0f, 0.0f);
        #pragma unroll
        for (int k2 = 0; k2 < CP2; ++k2) px2[k2] = z;
    }
    #pragma unroll
    for (int d = 0; d < DD; ++d) {
        const float* px = xb + d * LL + j0 + CPL * lane;
        float4 v0 = *reinterpret_cast<const float4*>(px);
        float4 v1 = *reinterpret_cast<const float4*>(px + 4);
        xp[d][0] = pack2(v0.x, v0.y);
        xp[d][1] = pack2(v0.z, v0.w);
        xp[d][2] = pack2(v1.x, v1.y);
        xp[d][3] = pack2(v1.z, v1.w);
        #pragma unroll
        for (int k2 = 0; k2 < CP2; ++k2)
            px2[k2] = ffma2(xp[d][k2], xp[d][k2], px2[k2]);
    }
    __syncthreads();   // pattern table visible to all warps

    float* outb = out + ((b * NP + n) * PP) * LOUT;
    float Dp[CPL];   // previous DP row for this warp's block

    // Full update of one row; reads/writes Dp; returns nothing (carry/output
    // handled by caller via Dp after the call; Dp[k] == cur[k] on return).
    auto rowcalc = [&](int i, float bl, float bm) {
        // cost row (alpha) via packed FMAs; pattern factors broadcast from smem
        u64 cc[CP2];
        {
            u64 p22 = ptp2[i];
            #pragma unroll
            for (int k2 = 0; k2 < CP2; ++k2) cc[k2] = fadd2(p22, px2[k2]);
        }
        #pragma unroll
        for (int d = 0; d < DD; ++d) {
            u64 pbb = pt[i][d];
            #pragma unroll
            for (int k2 = 0; k2 < CP2; ++k2)
                cc[k2] = ffma2(pbb, xp[d][k2], cc[k2]);
        }
        float c[CPL];
        #pragma unroll
        for (int k2 = 0; k2 < CP2; ++k2)
            unpack2(cc[k2], c[2 * k2], c[2 * k2 + 1]);

        // local inclusive composites (A = prefix sum of c, B = bound)
        float A[CPL], Bv[CPL];
        float shin = __shfl_up_sync(FULL, Dp[CPL - 1], 1);
        if (i == 0) {
            A[0] = c[0]; Bv[0] = BIGV;
            #pragma unroll
            for (int k = 1; k < CPL; ++k) { A[k] = A[k - 1] + c[k]; Bv[k] = BIGV; }
        } else {
            float m0 = fminf((lane == 0) ? bm : shin, Dp[0]);
            A[0]  = c[0];
            Bv[0] = c[0] + m0;
            #pragma unroll
            for (int k = 1; k < CPL; ++k) {
                float mk = fminf(Dp[k - 1], Dp[k]);
                A[k]  = A[k - 1] + c[k];
                Bv[k] = fminf(c[k] + mk, Bv[k - 1] + c[k]);
            }
        }

        // single composite warp scan over lane maps
        float Aw = A[CPL - 1], Bw = Bv[CPL - 1];
        #pragma unroll
        for (int o = 1; o < 32; o <<= 1) {
            float Au = __shfl_up_sync(FULL, Aw, o);
            float Bu = __shfl_up_sync(FULL, Bw, o);
            if (lane >= o) {
                Bw = fminf(Bw, Bu + Aw);  // uses pre-update Aw
                Aw = Aw + Au;
            }
        }
        float Ae = __shfl_up_sync(FULL, Aw, 1);
        float Be = __shfl_up_sync(FULL, Bw, 1);
        float vin = (lane == 0) ? bl : fminf(Be, bl + Ae);

        #pragma unroll
        for (int k = 0; k < CPL; ++k)
            Dp[k] = fminf(Bv[k], vin + A[k]);   // cur -> becomes prev row

        // output tail rows: cols 992..1023 = lanes 28..31 of last warp
        if (w == NBLK - 1 && lane >= 28) {
            float* po = outb + i * LOUT + (lane - 28) * CPL;
            *reinterpret_cast<float4*>(po)     = make_float4(Dp[0], Dp[1], Dp[2], Dp[3]);
            *reinterpret_cast<float4*>(po + 4) = make_float4(Dp[4], Dp[5], Dp[6], Dp[7]);
        }
    };

    #pragma unroll 1
    for (int i0 = 0; i0 < PP; i0 += 2) {
        // ---- consume: boundary carries for rows i0, i0+1 ----
        float bl0, bm0, bl1, bm1;
        if (w == 0) {
            bl0 = (i0 == 0) ? 0.0f : BIGV;   // D[0,0] seed enters as v
            bm0 = BIGV;                       // D[i-1][-1] always OOR at w==0
            bl1 = BIGV;
            bm1 = BIGV;
        } else {
            bar_pair(w);                      // rows 0..i0+1 of warp w-1 published
            bl0 = carry[w - 1][i0];
            bm0 = (i0 > 0) ? carry[w - 1][i0 - 1] : BIGV;
            bl1 = carry[w - 1][i0 + 1];
            bm1 = bl0;                        // = carry[w-1][i0]
        }

        rowcalc(i0, bl0, bm0);
        if (w < NBLK - 1 && lane == 31) carry[w][i0] = Dp[CPL - 1];

        rowcalc(i0 + 1, bl1, bm1);
        if (w < NBLK - 1 && lane == 31) carry[w][i0 + 1] = Dp[CPL - 1];

        // ---- produce: hand both rows to warp w+1 ----
        if (w < NBLK - 1) bar_pair(w + 1);
    }
}

extern "C" void kernel_launch(void* const* d_in, const int* in_sizes, int n_in,
                              void* d_out, int out_size) {
    const float* x     = (const float*)d_in[0];   // [32, 12, 1024]
    const float* patts = (const float*)d_in[1];   // [32, 12, 32]
    float* out = (float*)d_out;                   // [32, 32, 32, 32]
    (void)in_sizes; (void)n_in; (void)out_size;
    dtw_fused_kernel<<<NB * NP, 128>>>(x, patts, out);
}